// round 8
// baseline (speedup 1.0000x reference)
#include <cuda_runtime.h>
#include <cuda_bf16.h>
#include <math.h>
#include <stdint.h>

namespace {

constexpr int B_ = 32;
constexpr int N_ = 64;
constexpr int C_ = 128;
constexpr int M_ = 15;
constexpr int E_ = B_ * N_ * N_;   // 131072
constexpr float LN_EPS = 1e-5f;
constexpr int TSTR = 136;          // padded bf16 row stride (272B: conflict-free ldmatrix)
constexpr int WSEG = 128 * TSTR;   // elements per weight segment

// ---------------- device scratch --------------------------------------------
__device__ __align__(16) __nv_bfloat16 g_t1h[(size_t)E_ * C_];
__device__ __align__(16) __nv_bfloat16 g_t1l[(size_t)E_ * C_];
__device__ __align__(16) float g_row [B_ * N_ * C_];
__device__ __align__(16) float g_col [B_ * N_ * C_];
__device__ __align__(16) float g_diag[B_ * N_ * C_];
__device__ __align__(16) float g_A [B_ * N_ * C_];
__device__ __align__(16) float g_Bv[B_ * N_ * C_];
__device__ __align__(16) float g_D [B_ * N_ * C_];
__device__ __align__(16) float g_Cc[B_ * C_];
__device__ __align__(16) float g_Ec[B_ * C_];
__device__ __align__(16) float g_WT[M_ * C_ * C_];          // [m][c][o]
__device__ __align__(16) __nv_bfloat16 g_Wb[4 * WSEG];      // {W0hi,W0lo,W1hi,W1lo}

// ---------------- helpers ----------------------------------------------------
__device__ __forceinline__ float gelu_exact(float v) {
    return 0.5f * v * (1.0f + erff(v * 0.70710678118654752440f));
}
__device__ __forceinline__ uint32_t smem_to_u32(const void* p) {
    uint32_t a;
    asm("{ .reg .u64 t; cvta.to.shared.u64 t, %1; cvt.u32.u64 %0, t; }" : "=r"(a) : "l"(p));
    return a;
}
__device__ __forceinline__ void ldsm4(uint32_t* r, uint32_t addr) {
    asm volatile("ldmatrix.sync.aligned.m8n8.x4.shared.b16 {%0,%1,%2,%3}, [%4];"
                 : "=r"(r[0]), "=r"(r[1]), "=r"(r[2]), "=r"(r[3]) : "r"(addr));
}
__device__ __forceinline__ void mma16816(float* d, const uint32_t* a,
                                         uint32_t b0, uint32_t b1) {
    asm volatile("mma.sync.aligned.m16n8k16.row.col.f32.bf16.bf16.f32 "
                 "{%0,%1,%2,%3}, {%4,%5,%6,%7}, {%8,%9}, {%0,%1,%2,%3};"
                 : "+f"(d[0]), "+f"(d[1]), "+f"(d[2]), "+f"(d[3])
                 : "r"(a[0]), "r"(a[1]), "r"(a[2]), "r"(a[3]), "r"(b0), "r"(b1));
}
__device__ __forceinline__ void cvt_split4(float4 v, uint2& h, uint2& l) {
    __nv_bfloat162 h0 = __floats2bfloat162_rn(v.x, v.y);
    __nv_bfloat162 h1 = __floats2bfloat162_rn(v.z, v.w);
    float r0 = v.x - __bfloat162float(h0.x);
    float r1 = v.y - __bfloat162float(h0.y);
    float r2 = v.z - __bfloat162float(h1.x);
    float r3 = v.w - __bfloat162float(h1.y);
    __nv_bfloat162 l0 = __floats2bfloat162_rn(r0, r1);
    __nv_bfloat162 l1 = __floats2bfloat162_rn(r2, r3);
    h.x = *reinterpret_cast<uint32_t*>(&h0); h.y = *reinterpret_cast<uint32_t*>(&h1);
    l.x = *reinterpret_cast<uint32_t*>(&l0); l.y = *reinterpret_cast<uint32_t*>(&l1);
}
__device__ __forceinline__ uint32_t split_pack(float a, float b, uint32_t& lo) {
    __nv_bfloat162 h = __floats2bfloat162_rn(a, b);
    float r0 = a - __bfloat162float(h.x);
    float r1 = b - __bfloat162float(h.y);
    __nv_bfloat162 l = __floats2bfloat162_rn(r0, r1);
    lo = *reinterpret_cast<uint32_t*>(&l);
    return *reinterpret_cast<uint32_t*>(&h);
}

#define CP_ASYNC16(dst, src) \
    asm volatile("cp.async.cg.shared.global [%0], [%1], 16;" :: "r"(dst), "l"(src))
#define CP_COMMIT() asm volatile("cp.async.commit_group;" ::: "memory")
#define CP_WAIT0()  asm volatile("cp.async.wait_group 0;" ::: "memory")

// ---------------- K1: warp-MMA input GEMM + GELU + LN + row means -----------
constexpr int KI_WH = 0;
constexpr int KI_WL = 34816;
constexpr int KI_XH = 69632;
constexpr int KI_XL = 87040;
constexpr int KI_BI = 104448;
constexpr int KI_LG = 104960;
constexpr int KI_LB = 105472;
constexpr int KI_HR = 105984;
constexpr int KI_CS = 107008;
constexpr int KI_SM = 107520;

__global__ void __launch_bounds__(256) k_input(
        const float* __restrict__ x, const float* __restrict__ Wi,
        const float* __restrict__ bi, const float* __restrict__ lg,
        const float* __restrict__ lb) {
    extern __shared__ __align__(16) unsigned char smem[];
    const uint32_t sb = smem_to_u32(smem);
    const int tid = threadIdx.x, wid = tid >> 5, lane = tid & 31;
    const int j0 = (wid & 3) * 16, nh = wid >> 2;
    const int rg = lane >> 2, c2 = (lane & 3) * 2;

    for (int u = 0; u < 16; u++) {
        int idx = u * 256 + tid;
        int o = idx >> 5, c4 = (idx & 31) * 4;
        float4 v = *reinterpret_cast<const float4*>(Wi + o * C_ + c4);
        uint2 h, l; cvt_split4(v, h, l);
        uint32_t so = (uint32_t)(o * TSTR + c4) * 2;
        *reinterpret_cast<uint2*>(smem + KI_WH + so) = h;
        *reinterpret_cast<uint2*>(smem + KI_WL + so) = l;
    }
    if (tid < 128) {
        reinterpret_cast<float*>(smem + KI_BI)[tid] = bi[tid];
        reinterpret_cast<float*>(smem + KI_LG)[tid] = lg[tid];
        reinterpret_cast<float*>(smem + KI_LB)[tid] = lb[tid];
    }

    const uint32_t a_off = (uint32_t)((lane & 15) * TSTR + ((lane >> 4) << 3)) * 2;
    const uint32_t b_off = (uint32_t)((((lane >> 4) << 3) + (lane & 7)) * TSTR
                                      + (((lane >> 3) & 1) << 3)) * 2;
    const float* bi_s = reinterpret_cast<const float*>(smem + KI_BI);
    const float* lg_s = reinterpret_cast<const float*>(smem + KI_LG);
    const float* lb_s = reinterpret_cast<const float*>(smem + KI_LB);
    float* cs_s = reinterpret_cast<float*>(smem + KI_CS);
    float2* hr = reinterpret_cast<float2*>(smem + KI_HR);

    auto browi = [&](int kt, int np) -> uint32_t {
        return (uint32_t)((nh * 64 + np * 16) * TSTR) * 2 + b_off + (uint32_t)kt * 32;
    };

    for (int p = blockIdx.x; p < B_ * N_; p += gridDim.x) {
        __syncthreads();
        if (tid < 128) cs_s[tid] = 0.f;
        {
            const float* xs = x + (size_t)p * (N_ * C_);
            for (int u = 0; u < 8; u++) {
                int idx = u * 256 + tid;
                int r = idx >> 5, c4 = (idx & 31) * 4;
                float4 v = *reinterpret_cast<const float4*>(xs + r * C_ + c4);
                uint2 h, l; cvt_split4(v, h, l);
                uint32_t so = (uint32_t)(r * TSTR + c4) * 2;
                *reinterpret_cast<uint2*>(smem + KI_XH + so) = h;
                *reinterpret_cast<uint2*>(smem + KI_XL + so) = l;
            }
        }
        __syncthreads();

        float acc[8][4];
#pragma unroll
        for (int nt = 0; nt < 8; nt++)
#pragma unroll
            for (int q = 0; q < 4; q++) acc[nt][q] = 0.f;

        // B double-buffer: preload (kt=0, np=0)
        uint32_t whA[4], wlA[4], whB[4], wlB[4];
        ldsm4(whA, sb + KI_WH + browi(0, 0));
        ldsm4(wlA, sb + KI_WL + browi(0, 0));

#pragma unroll 1
        for (int kt = 0; kt < 8; kt++) {
            const uint32_t arow = (uint32_t)(j0 * TSTR) * 2 + a_off + (uint32_t)kt * 32;
            uint32_t xh[4], xl[4];
            ldsm4(xh, sb + KI_XH + arow);
            ldsm4(xl, sb + KI_XL + arow);
#pragma unroll
            for (int np = 0; np < 4; np++) {
                const uint32_t* wh = (np & 1) ? whB : whA;
                const uint32_t* wl = (np & 1) ? wlB : wlA;
                uint32_t* nwh = (np & 1) ? whA : whB;
                uint32_t* nwl = (np & 1) ? wlA : wlB;
                // prefetch next B fragments before the dependent MMAs
                if (np < 3) {
                    ldsm4(nwh, sb + KI_WH + browi(kt, np + 1));
                    ldsm4(nwl, sb + KI_WL + browi(kt, np + 1));
                } else if (kt < 7) {
                    ldsm4(nwh, sb + KI_WH + browi(kt + 1, 0));
                    ldsm4(nwl, sb + KI_WL + browi(kt + 1, 0));
                }
#pragma unroll
                for (int e = 0; e < 2; e++) {
                    float* d = acc[np * 2 + e];
                    const int rgi = e * 2;
                    mma16816(d, xh, wh[rgi], wh[rgi + 1]);
                    mma16816(d, xh, wl[rgi], wl[rgi + 1]);
                    mma16816(d, xl, wh[rgi], wh[rgi + 1]);
                }
            }
        }

        // ---- epilogue: bias + GELU, LN stats ----
        float sa = 0.f, ssa = 0.f, sbm = 0.f, ssb = 0.f;
#pragma unroll
        for (int nt = 0; nt < 8; nt++) {
            const int o = nh * 64 + nt * 8 + c2;
            const float b0 = bi_s[o], b1 = bi_s[o + 1];
            acc[nt][0] = gelu_exact(acc[nt][0] + b0);
            acc[nt][1] = gelu_exact(acc[nt][1] + b1);
            acc[nt][2] = gelu_exact(acc[nt][2] + b0);
            acc[nt][3] = gelu_exact(acc[nt][3] + b1);
            sa  += acc[nt][0] + acc[nt][1];
            ssa += acc[nt][0] * acc[nt][0] + acc[nt][1] * acc[nt][1];
            sbm += acc[nt][2] + acc[nt][3];
            ssb += acc[nt][2] * acc[nt][2] + acc[nt][3] * acc[nt][3];
        }
#pragma unroll
        for (int off = 1; off <= 2; off <<= 1) {
            sa  += __shfl_xor_sync(0xffffffffu, sa,  off);
            ssa += __shfl_xor_sync(0xffffffffu, ssa, off);
            sbm += __shfl_xor_sync(0xffffffffu, sbm, off);
            ssb += __shfl_xor_sync(0xffffffffu, ssb, off);
        }
        if ((lane & 3) == 0) {
            hr[(j0 + rg) * 2 + nh]     = make_float2(sa, ssa);
            hr[(j0 + rg + 8) * 2 + nh] = make_float2(sbm, ssb);
        }
        __syncthreads();
        const int ja = j0 + rg, jb = j0 + rg + 8;
        float2 ha0 = hr[ja * 2 + 0], ha1 = hr[ja * 2 + 1];
        float2 hb0 = hr[jb * 2 + 0], hb1 = hr[jb * 2 + 1];
        const float mua = (ha0.x + ha1.x) * (1.0f / C_);
        const float inva = rsqrtf((ha0.y + ha1.y) * (1.0f / C_) - mua * mua + LN_EPS);
        const float mub = (hb0.x + hb1.x) * (1.0f / C_);
        const float invb = rsqrtf((hb0.y + hb1.y) * (1.0f / C_) - mub * mub + LN_EPS);

        uint32_t* th32 = reinterpret_cast<uint32_t*>(g_t1h);
        uint32_t* tl32 = reinterpret_cast<uint32_t*>(g_t1l);
        const size_t rba = ((size_t)p * N_ + ja) * (C_ / 2);
        const size_t rbb = ((size_t)p * N_ + jb) * (C_ / 2);
#pragma unroll
        for (int nt = 0; nt < 8; nt++) {
            const int o = nh * 64 + nt * 8 + c2;
            const float g0 = lg_s[o], g1 = lg_s[o + 1];
            const float z0 = lb_s[o], z1 = lb_s[o + 1];
            float n0 = (acc[nt][0] - mua) * inva * g0 + z0;
            float n1 = (acc[nt][1] - mua) * inva * g1 + z1;
            float n2 = (acc[nt][2] - mub) * invb * g0 + z0;
            float n3 = (acc[nt][3] - mub) * invb * g1 + z1;
            uint32_t lo;
            uint32_t hi = split_pack(n0, n1, lo);
            th32[rba + (o >> 1)] = hi; tl32[rba + (o >> 1)] = lo;
            hi = split_pack(n2, n3, lo);
            th32[rbb + (o >> 1)] = hi; tl32[rbb + (o >> 1)] = lo;
            float cs0 = n0 + n2, cs1 = n1 + n3;
#pragma unroll
            for (int off = 4; off <= 16; off <<= 1) {
                cs0 += __shfl_xor_sync(0xffffffffu, cs0, off);
                cs1 += __shfl_xor_sync(0xffffffffu, cs1, off);
            }
            if (rg == 0) {
                atomicAdd(&cs_s[o], cs0);
                atomicAdd(&cs_s[o + 1], cs1);
            }
        }
        __syncthreads();
        if (tid < 128) g_row[p * C_ + tid] = cs_s[tid] * (1.0f / N_);
    }
}

// ---------------- K2: coeffs (+ split bf16 W0/W1) + col means + diag --------
__global__ void __launch_bounds__(512) k_mix(
        const float* __restrict__ c00, const float* __restrict__ c01,
        const float* __restrict__ c10, const float* __restrict__ c11) {
    const int bx = blockIdx.x, tid = threadIdx.x;
    if (bx < 120) {
#pragma unroll
        for (int u = 0; u < 4; u++) {
            int idx = bx * 2048 + u * 512 + tid;
            int o = idx & 127, c = (idx >> 7) & 127, m = idx >> 14;
            float v = c00[o * M_ + m] * c10[o * C_ + c] + c01[c * M_ + m] * c11[o * C_ + c];
            g_WT[idx] = v;
            if (m < 2) {
                __nv_bfloat16 hb = __float2bfloat16_rn(v);
                float rr = v - __bfloat162float(hb);
                __nv_bfloat16 lo = __float2bfloat16_rn(rr);
                g_Wb[(m * 2 + 0) * WSEG + o * TSTR + c] = hb;
                g_Wb[(m * 2 + 1) * WSEG + o * TSTR + c] = lo;
            }
        }
    } else {
        int p = (bx - 120) * 8 + (tid >> 6);
        int co = (tid & 63) * 2;
        int b = p >> 6, q = p & 63;
        const uint32_t* th32 = reinterpret_cast<const uint32_t*>(g_t1h);
        const uint32_t* tl32 = reinterpret_cast<const uint32_t*>(g_t1l);
        float s0 = 0.f, s1 = 0.f;
#pragma unroll 4
        for (int i2 = 0; i2 < N_; i2++) {
            size_t idx = ((size_t)((b * N_ + i2) * N_ + q) * C_ + co) >> 1;
            uint32_t hv = th32[idx], lv = tl32[idx];
            __nv_bfloat162 hb = *reinterpret_cast<__nv_bfloat162*>(&hv);
            __nv_bfloat162 lb2 = *reinterpret_cast<__nv_bfloat162*>(&lv);
            s0 += __bfloat162float(hb.x) + __bfloat162float(lb2.x);
            s1 += __bfloat162float(hb.y) + __bfloat162float(lb2.y);
        }
        g_col[p * C_ + co]     = s0 * (1.0f / N_);
        g_col[p * C_ + co + 1] = s1 * (1.0f / N_);
        size_t di = ((size_t)((b * N_ + q) * N_ + q) * C_ + co) >> 1;
        uint32_t hv = th32[di], lv = tl32[di];
        __nv_bfloat162 hb = *reinterpret_cast<__nv_bfloat162*>(&hv);
        __nv_bfloat162 lb2 = *reinterpret_cast<__nv_bfloat162*>(&lv);
        g_diag[p * C_ + co]     = __bfloat162float(hb.x) + __bfloat162float(lb2.x);
        g_diag[p * C_ + co + 1] = __bfloat162float(hb.y) + __bfloat162float(lb2.y);
    }
}

// ---------------- K3: A,Bv,D + Cc,Ec ----------------------------------------
__global__ void __launch_bounds__(512) k_abd_ce() {
    const int tid = threadIdx.x;
    if (blockIdx.x < 128) {
        __shared__ float s_in[3 * 16 * C_];
        float* sd = s_in;
        float* sr = s_in + 16 * C_;
        float* sc = s_in + 32 * C_;
        const int rb = blockIdx.x * 16;
        for (int idx = tid; idx < 16 * C_; idx += 512) {
            sd[idx] = g_diag[rb * C_ + idx];
            sr[idx] = g_row [rb * C_ + idx];
            sc[idx] = g_col [rb * C_ + idx];
        }
        __syncthreads();
        const int o = tid & 127, grp = tid >> 7;
        const float* W[9] = {
            g_WT + 2 * C_ * C_, g_WT + 4 * C_ * C_, g_WT + 6 * C_ * C_,
            g_WT + 3 * C_ * C_, g_WT + 5 * C_ * C_, g_WT + 7 * C_ * C_,
            g_WT + 10 * C_ * C_, g_WT + 11 * C_ * C_, g_WT + 12 * C_ * C_
        };
        float acc[4][3];
#pragma unroll
        for (int r = 0; r < 4; r++) { acc[r][0] = acc[r][1] = acc[r][2] = 0.f; }
#pragma unroll 1
        for (int c0 = 0; c0 < C_; c0 += 4) {
            float w[4][9];
#pragma unroll
            for (int u = 0; u < 4; u++) {
                int wi = (c0 + u) * C_ + o;
#pragma unroll
                for (int m = 0; m < 9; m++) w[u][m] = W[m][wi];
            }
#pragma unroll
            for (int u = 0; u < 4; u++) {
                int c = c0 + u;
#pragma unroll
                for (int r = 0; r < 4; r++) {
                    int rr = grp * 4 + r;
                    float d = sd[rr * C_ + c], ro = sr[rr * C_ + c], co = sc[rr * C_ + c];
                    acc[r][0] = fmaf(w[u][0], d, fmaf(w[u][1], ro, fmaf(w[u][2], co, acc[r][0])));
                    acc[r][1] = fmaf(w[u][3], d, fmaf(w[u][4], ro, fmaf(w[u][5], co, acc[r][1])));
                    acc[r][2] = fmaf(w[u][6], d, fmaf(w[u][7], ro, fmaf(w[u][8], co, acc[r][2])));
                }
            }
        }
#pragma unroll
        for (int r = 0; r < 4; r++) {
            int rr = rb + grp * 4 + r;
            g_A [rr * C_ + o] = acc[r][0];
            g_Bv[rr * C_ + o] = acc[r][1];
            g_D [rr * C_ + o] = acc[r][2];
        }
    } else {
        __shared__ float str[C_], sto[C_], red[8][C_];
        const int b = blockIdx.x - 128;
        if (tid < C_) {
            float st = 0.f, so = 0.f;
#pragma unroll 4
            for (int q = 0; q < N_; q++) {
                st += g_diag[(b * N_ + q) * C_ + tid];
                so += g_row [(b * N_ + q) * C_ + tid];
            }
            str[tid] = st * (1.0f / N_);
            sto[tid] = so * (1.0f / N_);
        }
        __syncthreads();
        const int o = tid & 127, grp = tid >> 7;
        const float* W8  = g_WT + 8  * C_ * C_;
        const float* W9  = g_WT + 9  * C_ * C_;
        const float* W13 = g_WT + 13 * C_ * C_;
        const float* W14 = g_WT + 14 * C_ * C_;
        float a = 0.f, e = 0.f;
        for (int c = grp * 32; c < grp * 32 + 32; c++) {
            int wi = c * C_ + o;
            float tr = str[c], to = sto[c];
            a = fmaf(W8 [wi], tr, fmaf(W9 [wi], to, a));
            e = fmaf(W13[wi], tr, fmaf(W14[wi], to, e));
        }
        red[grp][o] = a; red[4 + grp][o] = e;
        __syncthreads();
        if (tid < C_) {
            g_Cc[b * C_ + tid] = red[0][tid] + red[1][tid] + red[2][tid] + red[3][tid];
            g_Ec[b * C_ + tid] = red[4][tid] + red[5][tid] + red[6][tid] + red[7][tid];
        }
    }
}

// ---------------- K4: warp-MMA main GEMM pair (512 threads, pipelined) ------
constexpr int SMB_W0H = 0;
constexpr int SMB_W0L = 34816;
constexpr int SMB_W1H = 69632;
constexpr int SMB_W1L = 104448;
constexpr int SMB_T1H = 139264;
constexpr int SMB_T1L = 156672;
constexpr int SMB_T2H = 174080;
constexpr int SMB_T2L = 191488;
constexpr int SM_MAIN = 208896;

__global__ void __launch_bounds__(512) k_main(float* __restrict__ out) {
    extern __shared__ __align__(16) unsigned char smem[];
    const uint32_t sb = smem_to_u32(smem);
    const int tid = threadIdx.x, wid = tid >> 5, lane = tid & 31;
    const int j0 = (wid & 3) * 16;       // 4 j-tiles of 16 rows
    const int nq = wid >> 2;             // 4 n-quarters of 32 cols

    {   // resident weights
        const uint4* src = reinterpret_cast<const uint4*>(g_Wb);
        uint4* dst = reinterpret_cast<uint4*>(smem);
        for (int i = tid; i < 4 * WSEG * 2 / 16; i += 512) dst[i] = src[i];
    }

    const uint32_t a_off = (uint32_t)((lane & 15) * TSTR + ((lane >> 4) << 3)) * 2;
    const uint32_t b_off = (uint32_t)((((lane >> 4) << 3) + (lane & 7)) * TSTR
                                      + (((lane >> 3) & 1) << 3)) * 2;

    auto brow = [&](int kt, int npi) -> uint32_t {   // np = nq*2 + npi
        return (uint32_t)(((nq * 2 + npi) * 16) * TSTR) * 2 + b_off + (uint32_t)kt * 32;
    };

    auto stage = [&](int p) {   // 8 cp.async x 16B per thread (512 threads)
        const int b = p >> 6, i = p & 63;
        const char* s1h = reinterpret_cast<const char*>(g_t1h + (size_t)p * (N_ * C_));
        const char* s1l = reinterpret_cast<const char*>(g_t1l + (size_t)p * (N_ * C_));
#pragma unroll
        for (int u = 0; u < 2; u++) {
            int ch = u * 512 + tid;         // 0..1023
            int r = ch >> 4, c = ch & 15;
            uint32_t dso = (uint32_t)(r * TSTR + c * 8) * 2;
            CP_ASYNC16(sb + SMB_T1H + dso, s1h + ch * 16);
            CP_ASYNC16(sb + SMB_T1L + dso, s1l + ch * 16);
            const size_t r2 = ((size_t)((b * N_ + r) * N_ + i)) * C_;
            CP_ASYNC16(sb + SMB_T2H + dso, reinterpret_cast<const char*>(g_t1h + r2) + c * 16);
            CP_ASYNC16(sb + SMB_T2L + dso, reinterpret_cast<const char*>(g_t1l + r2) + c * 16);
        }
    };

    int p = blockIdx.x;
    if (p < B_ * N_) { stage(p); CP_COMMIT(); }
    CP_WAIT0();
    __syncthreads();

    for (; p < B_ * N_; p += gridDim.x) {
        const int b = p >> 6, i = p & 63;

        float acc[4][4];
#pragma unroll
        for (int nt = 0; nt < 4; nt++)
#pragma unroll
            for (int q = 0; q < 4; q++) acc[nt][q] = 0.f;

        // B double-buffer: preload (kt=0, npi=0) into buf A
        uint32_t w0hA[4], w0lA[4], w1hA[4], w1lA[4];
        uint32_t w0hB[4], w0lB[4], w1hB[4], w1lB[4];
        ldsm4(w0hA, sb + SMB_W0H + brow(0, 0));
        ldsm4(w0lA, sb + SMB_W0L + brow(0, 0));
        ldsm4(w1hA, sb + SMB_W1H + brow(0, 0));
        ldsm4(w1lA, sb + SMB_W1L + brow(0, 0));

#pragma unroll 1
        for (int kt = 0; kt < 8; kt++) {
            const uint32_t arow = (uint32_t)(j0 * TSTR) * 2 + a_off + (uint32_t)kt * 32;
            uint32_t a1h[4], a1l[4], a2h[4], a2l[4];
            ldsm4(a1h, sb + SMB_T1H + arow);
            ldsm4(a1l, sb + SMB_T1L + arow);
            ldsm4(a2h, sb + SMB_T2H + arow);
            ldsm4(a2l, sb + SMB_T2L + arow);

            // ---- npi = 0: prefetch (kt,1) into buf B; compute with buf A ----
            ldsm4(w0hB, sb + SMB_W0H + brow(kt, 1));
            ldsm4(w0lB, sb + SMB_W0L + brow(kt, 1));
            ldsm4(w1hB, sb + SMB_W1H + brow(kt, 1));
            ldsm4(w1lB, sb + SMB_W1L + brow(kt, 1));
#pragma unroll
            for (int e = 0; e < 2; e++) {
                float* d = acc[e];
                const int rgi = e * 2;
                mma16816(d, a1h, w0hA[rgi], w0hA[rgi + 1]);
                mma16816(d, a1h, w0lA[rgi], w0lA[rgi + 1]);
                mma16816(d, a1l, w0hA[rgi], w0hA[rgi + 1]);
                mma16816(d, a2h, w1hA[rgi], w1hA[rgi + 1]);
                mma16816(d, a2h, w1lA[rgi], w1lA[rgi + 1]);
                mma16816(d, a2l, w1hA[rgi], w1hA[rgi + 1]);
            }
            // ---- npi = 1: prefetch (kt+1,0) into buf A; compute with buf B ----
            if (kt < 7) {
                ldsm4(w0hA, sb + SMB_W0H + brow(kt + 1, 0));
                ldsm4(w0lA, sb + SMB_W0L + brow(kt + 1, 0));
                ldsm4(w1hA, sb + SMB_W1H + brow(kt + 1, 0));
                ldsm4(w1lA, sb + SMB_W1L + brow(kt + 1, 0));
            }
#pragma unroll
            for (int e = 0; e < 2; e++) {
                float* d = acc[2 + e];
                const int rgi = e * 2;
                mma16816(d, a1h, w0hB[rgi], w0hB[rgi + 1]);
                mma16816(d, a1h, w0lB[rgi], w0lB[rgi + 1]);
                mma16816(d, a1l, w0hB[rgi], w0hB[rgi + 1]);
                mma16816(d, a2h, w1hB[rgi], w1hB[rgi + 1]);
                mma16816(d, a2h, w1lB[rgi], w1lB[rgi + 1]);
                mma16816(d, a2l, w1hB[rgi], w1hB[rgi + 1]);
            }
        }
        __syncthreads();
        const int pn = p + gridDim.x;
        if (pn < B_ * N_) { stage(pn); CP_COMMIT(); }

        // ---- epilogue ----
        {
            const int rg = lane >> 2;
            const int c2 = (lane & 3) * 2;
            const int ja = j0 + rg, jb = j0 + rg + 8;
            const float* Ap  = g_A  + (size_t)p * C_;
            const float* Ccp = g_Cc + (size_t)b * C_;
            const float* Dp  = g_D  + (size_t)p * C_;
            const float* Ep  = g_Ec + (size_t)b * C_;
            const float* Bva = g_Bv + ((size_t)(b * N_ + ja)) * C_;
            const float* Bvb = g_Bv + ((size_t)(b * N_ + jb)) * C_;
            float* outa = out + ((size_t)p * N_ + ja) * C_;
            float* outb = out + ((size_t)p * N_ + jb) * C_;
            const bool da = (ja == i), db = (jb == i);
#pragma unroll
            for (int nt = 0; nt < 4; nt++) {
                const int o = nq * 32 + nt * 8 + c2;
                float2 av = *reinterpret_cast<const float2*>(Ap + o);
                float2 cv = *reinterpret_cast<const float2*>(Ccp + o);
                const float addx = av.x + cv.x, addy = av.y + cv.y;
                float2 dd, ee;
                if (da || db) {
                    dd = *reinterpret_cast<const float2*>(Dp + o);
                    ee = *reinterpret_cast<const float2*>(Ep + o);
                }
                {
                    float2 bv = *reinterpret_cast<const float2*>(Bva + o);
                    float e0 = acc[nt][0] + addx + bv.x;
                    float e1 = acc[nt][1] + addy + bv.y;
                    if (da) { e0 += dd.x + ee.x; e1 += dd.y + ee.y; }
                    float2 o2; o2.x = gelu_exact(e0); o2.y = gelu_exact(e1);
                    *reinterpret_cast<float2*>(outa + o) = o2;
                }
                {
                    float2 bv = *reinterpret_cast<const float2*>(Bvb + o);
                    float e0 = acc[nt][2] + addx + bv.x;
                    float e1 = acc[nt][3] + addy + bv.y;
                    if (db) { e0 += dd.x + ee.x; e1 += dd.y + ee.y; }
                    float2 o2; o2.x = gelu_exact(e0); o2.y = gelu_exact(e1);
                    *reinterpret_cast<float2*>(outb + o) = o2;
                }
            }
        }
        CP_WAIT0();
        __syncthreads();
    }
}

} // anonymous namespace

// ---------------- launch -----------------------------------------------------
extern "C" void kernel_launch(void* const* d_in, const int* in_sizes, int n_in,
                              void* d_out, int out_size) {
    const float* x   = (const float*)d_in[0];
    const float* Wi  = (const float*)d_in[3];
    const float* bi  = (const float*)d_in[4];
    const float* lg  = (const float*)d_in[5];
    const float* lb  = (const float*)d_in[6];
    const float* c00 = (const float*)d_in[7];
    const float* c01 = (const float*)d_in[8];
    const float* c10 = (const float*)d_in[9];
    const float* c11 = (const float*)d_in[10];
    float* out = (float*)d_out;

    cudaFuncSetAttribute(k_input, cudaFuncAttributeMaxDynamicSharedMemorySize, KI_SM);
    cudaFuncSetAttribute(k_main,  cudaFuncAttributeMaxDynamicSharedMemorySize, SM_MAIN);

    k_input <<<296, 256, KI_SM>>>(x, Wi, bi, lg, lb);
    k_mix   <<<376, 512>>>(c00, c01, c10, c11);
    k_abd_ce<<<160, 512>>>();
    k_main  <<<148, 512, SM_MAIN>>>(out);
}